// round 15
// baseline (speedup 1.0000x reference)
#include <cuda_runtime.h>
#include <cuda_fp16.h>
#include <math.h>
#include <stdint.h>

// ---------------------------------------------------------------------------
// Problem constants
// ---------------------------------------------------------------------------
#define N0 100000
#define N1 50000
#define HID 128
#define NH 4
#define HD 32
#define NL 2

#define LD0 384   // type0 weights: Q | K_r0 | V_r0
#define LD1 640   // type1 weights: Q | K_r1 | V_r1 | K_r2 | V_r2
#define KV0 256   // halves per type0 kv row (k@0, v@128)
#define KV1 512   // halves per type1 kv row (k1@0, v1@128, k2@256, v2@384)

#define NB0 ((N0 + 127) / 128)
#define NB1 ((N1 + 127) / 128)

#define AGGR_FLOATS ((size_t)(N0 + 2 * N1) * HID)
#define SSUM_FLOATS ((size_t)3 * N0 * NH)

// ---------------------------------------------------------------------------
// Static device scratch
// ---------------------------------------------------------------------------
__device__ __half g_q0[(size_t)N0 * HID];
__device__ __half g_q1[(size_t)N1 * HID];
__device__ __half g_kv0[(size_t)N0 * KV0];
__device__ __half g_kv1[(size_t)N1 * KV1];
__device__ float  g_agg[(size_t)(N0 + N1) * HID];
__device__ float  g_aggr[AGGR_FLOATS + SSUM_FLOATS];
__device__ __half g_wcat0[NL * HID * LD0];   // transposed [n][k] fp16
__device__ __half g_wcat1[NL * HID * LD1];
__device__ float  g_bcat0[NL * LD0];
__device__ float  g_bcat1[NL * LD1];
__device__ __half g_win[2 * HID * HID];      // transposed fp16
__device__ __half g_wa[NL * 2 * HID * HID];  // transposed fp16

// ---------------------------------------------------------------------------
// Helpers
// ---------------------------------------------------------------------------
__device__ __forceinline__ float gelu_exact(float x) {
    return 0.5f * x * (1.0f + erff(x * 0.7071067811865476f));
}
__device__ __forceinline__ unsigned pack_h2(float a, float b) {
    __half2 h = __floats2half2_rn(a, b);
    return *reinterpret_cast<unsigned*>(&h);
}
__device__ __forceinline__ void mma_f16(float* c, const unsigned* a, const unsigned* b) {
    asm("mma.sync.aligned.m16n8k16.row.col.f32.f16.f16.f32 "
        "{%0,%1,%2,%3}, {%4,%5,%6,%7}, {%8,%9}, {%0,%1,%2,%3};"
        : "+f"(c[0]), "+f"(c[1]), "+f"(c[2]), "+f"(c[3])
        : "r"(a[0]), "r"(a[1]), "r"(a[2]), "r"(a[3]), "r"(b[0]), "r"(b[1]));
}
__device__ __forceinline__ void cpa16(float* dst, const float* src) {
    unsigned d = (unsigned)__cvta_generic_to_shared(dst);
    asm volatile("cp.async.cg.shared.global [%0], [%1], 16;" :: "r"(d), "l"(src));
}
__device__ __forceinline__ void cpa8h(__half* dst, const __half* src) {
    unsigned d = (unsigned)__cvta_generic_to_shared(dst);
    asm volatile("cp.async.ca.shared.global [%0], [%1], 8;" :: "r"(d), "l"(src));
}
__device__ __forceinline__ void cp_commit() { asm volatile("cp.async.commit_group;"); }
template <int N>
__device__ __forceinline__ void cp_wait() {
    asm volatile("cp.async.wait_group %0;" :: "n"(N));
}

// ---------------------------------------------------------------------------
// Paired FP16 TC GEMM (m16n8k16, fp32 accum). A fp32 (converted at fragment
// load), B fp16 transposed [n][k]. cp.async 3-stage, 128x128x16, 512 threads.
//   EPI: 0 none, 1 relu, 2 skip-blend
//   OUTH=1: all tiles write fp16 (y==0 -> Cq, y>=1 -> Ckv at col-128)
// ---------------------------------------------------------------------------
#define GBM 128
#define GBN 128
#define AS_LD 20                 // floats per A row
#define BS_LD 24                 // halves per B row (pad; conflict-free)
#define A_STG (128 * AS_LD)      // floats
#define B_STG (128 * BS_LD)      // halves
#define GEMM_SMEM (3 * A_STG * 4 + 3 * B_STG * 2)

struct GemmSide {
    const float* A; int lda;
    const __half* B;             // [n_total][128] fp16
    const float* bias;
    float* C; int ldc;
    __half* Cq;
    __half* Ckv; int ldkv;
    int M; int nby;
    const float* hprev; int ldh;
    const float* skipPtr;
};
struct GemmPair { GemmSide s[2]; int nb0; };

template <int EPI, int OUTH>
__global__ __launch_bounds__(512, 2) void gemm_tc(GemmPair P)
{
    extern __shared__ float smemf[];
    float*  AsBase = smemf;
    __half* BsBase = reinterpret_cast<__half*>(smemf + 3 * A_STG);

    const int side = (blockIdx.x >= (unsigned)P.nb0);
    const GemmSide S = P.s[side];
    const int bx = side ? (blockIdx.x - P.nb0) : blockIdx.x;
    if ((int)blockIdx.y >= S.nby) return;

    const int tid  = threadIdx.x;
    const int wid  = tid >> 5;
    const int lane = tid & 31;
    const int row0 = bx * GBM;
    const int col0 = blockIdx.y * GBN;
    const int wm0  = (wid >> 2) * 32;
    const int wn0  = (wid & 3) * 32;
    const int g    = lane >> 2;
    const int tig  = lane & 3;

    const int rA = tid >> 2, kcA = (tid & 3) << 2;       // A: 16B per thread
    const int nB = tid >> 2, koB = (tid & 3) << 2;       // B: 8B (4 halves)
    int gArow = row0 + rA; if (gArow >= S.M) gArow = S.M - 1;
    const float*  gA = S.A + (size_t)gArow * S.lda + kcA;
    const __half* gB = S.B + (size_t)(col0 + nB) * HID + koB;

    auto stage_load = [&](int s, int kt) {
        cpa16(AsBase + s * A_STG + rA * AS_LD + kcA, gA + kt * 16);
        cpa8h(BsBase + s * B_STG + nB * BS_LD + koB, gB + kt * 16);
    };

    stage_load(0, 0); cp_commit();
    stage_load(1, 1); cp_commit();

    float acc[2][4][4];
#pragma unroll
    for (int i = 0; i < 2; i++)
#pragma unroll
        for (int j = 0; j < 4; j++)
#pragma unroll
            for (int q = 0; q < 4; q++) acc[i][j][q] = 0.f;

#pragma unroll
    for (int kt = 0; kt < 8; kt++) {
        cp_wait<1>();
        __syncthreads();
        if (kt + 2 < 8) stage_load((kt + 2) % 3, kt + 2);
        cp_commit();

        const float*  Ast = AsBase + (kt % 3) * A_STG;
        const __half* Bst = BsBase + (kt % 3) * B_STG;

        unsigned aR[2][4], bR[4][2];
#pragma unroll
        for (int mt = 0; mt < 2; mt++) {
            int m = wm0 + mt * 16 + g;
            float2 f0 = *reinterpret_cast<const float2*>(&Ast[(size_t)m * AS_LD + 2 * tig]);
            float2 f2 = *reinterpret_cast<const float2*>(&Ast[(size_t)m * AS_LD + 2 * tig + 8]);
            float2 f1 = *reinterpret_cast<const float2*>(&Ast[(size_t)(m + 8) * AS_LD + 2 * tig]);
            float2 f3 = *reinterpret_cast<const float2*>(&Ast[(size_t)(m + 8) * AS_LD + 2 * tig + 8]);
            aR[mt][0] = pack_h2(f0.x, f0.y);
            aR[mt][1] = pack_h2(f1.x, f1.y);
            aR[mt][2] = pack_h2(f2.x, f2.y);
            aR[mt][3] = pack_h2(f3.x, f3.y);
        }
#pragma unroll
        for (int nt = 0; nt < 4; nt++) {
            int n = wn0 + nt * 8 + g;
            bR[nt][0] = *reinterpret_cast<const unsigned*>(&Bst[(size_t)n * BS_LD + 2 * tig]);
            bR[nt][1] = *reinterpret_cast<const unsigned*>(&Bst[(size_t)n * BS_LD + 2 * tig + 8]);
        }
#pragma unroll
        for (int mt = 0; mt < 2; mt++)
#pragma unroll
            for (int nt = 0; nt < 4; nt++)
                mma_f16(acc[mt][nt], aR[mt], bR[nt]);
    }

    float sgate = 0.f;
    if (EPI == 2) sgate = 1.f / (1.f + expf(-(*S.skipPtr)));

#pragma unroll
    for (int mt = 0; mt < 2; mt++) {
#pragma unroll
        for (int rr = 0; rr < 2; rr++) {
            int grow = row0 + wm0 + mt * 16 + g + rr * 8;
            if (grow >= S.M) continue;
#pragma unroll
            for (int nt = 0; nt < 4; nt++) {
                int col = col0 + wn0 + nt * 8 + 2 * tig;
                float v0 = acc[mt][nt][rr * 2 + 0] + S.bias[col];
                float v1 = acc[mt][nt][rr * 2 + 1] + S.bias[col + 1];
                if (EPI == 1) { v0 = fmaxf(v0, 0.f); v1 = fmaxf(v1, 0.f); }
                if (EPI == 2) {
                    const float* hp = S.hprev + (size_t)grow * S.ldh + col;
                    v0 = sgate * v0 + (1.f - sgate) * hp[0];
                    v1 = sgate * v1 + (1.f - sgate) * hp[1];
                }
                if (OUTH == 1) {
                    __half2 hv = __floats2half2_rn(v0, v1);
                    if (blockIdx.y == 0)
                        *reinterpret_cast<__half2*>(S.Cq + (size_t)grow * HID + col) = hv;
                    else
                        *reinterpret_cast<__half2*>(
                            S.Ckv + (size_t)grow * S.ldkv + (col - 128)) = hv;
                } else {
                    *reinterpret_cast<float2*>(S.C + (size_t)grow * S.ldc + col) =
                        make_float2(v0, v1);
                }
            }
        }
    }
}

// ---------------------------------------------------------------------------
// Weight prep: 22 sections, outputs TRANSPOSED fp16 [n][k]. A==nullptr -> copy.
// ---------------------------------------------------------------------------
struct WPrepSec {
    const float* W; const float* b; const float* A;
    __half* Wd; float* bd;
};
struct WPrepN { WPrepSec s[22]; };

__global__ void prep_w_k(WPrepN P)
{
    WPrepSec p = P.s[blockIdx.y];
    int col = threadIdx.x;
    int i = blockIdx.x;
    if (p.A == nullptr) {
        if (i < HID)
            p.Wd[(size_t)col * HID + i] = __float2half(p.W[(size_t)i * HID + col]);
        else if (p.bd) p.bd[col] = p.b[col];
        return;
    }
    int h = col >> 5, e = col & 31;
    const float* Ah = p.A + h * HD * HD;
    if (i < HID) {
        const float* wrow = p.W + (size_t)i * HID + h * HD;
        float acc = 0.f;
#pragma unroll
        for (int d = 0; d < HD; d++) acc = fmaf(wrow[d], Ah[d * HD + e], acc);
        p.Wd[(size_t)col * HID + i] = __float2half(acc);
    } else if (p.bd) {
        const float* brow = p.b + h * HD;
        float acc = 0.f;
#pragma unroll
        for (int d = 0; d < HD; d++) acc = fmaf(brow[d], Ah[d * HD + e], acc);
        p.bd[col] = acc;
    }
}

// ---------------------------------------------------------------------------
// Single-pass fused edge kernel (warp per edge). q, k, v all fp16.
// ---------------------------------------------------------------------------
struct EdgeRel {
    const int* src; const int* dst;
    const __half* q;
    const __half* k; const __half* v; int ldkv;
    const float* prel;
    float* ssum; float* aggr;
};
struct Edge3 { EdgeRel r[3]; int off1, off2, total; };

__global__ void edge_fused_k(Edge3 P)
{
    int w = blockIdx.x * (blockDim.x >> 5) + (threadIdx.x >> 5);
    if (w >= P.total) return;
    int lane = threadIdx.x & 31;
    int ri = (w >= P.off1) + (w >= P.off2);
    int base = ri == 0 ? 0 : (ri == 1 ? P.off1 : P.off2);
    EdgeRel R = P.r[ri];
    int e = w - base;
    int s = __ldg(&R.src[e]), d = __ldg(&R.dst[e]);
    uint2 qraw = *reinterpret_cast<const uint2*>(R.q + (size_t)d * HID + lane * 4);
    float2 q0 = __half22float2(*reinterpret_cast<__half2*>(&qraw.x));
    float2 q1 = __half22float2(*reinterpret_cast<__half2*>(&qraw.y));
    uint2 kraw = *reinterpret_cast<const uint2*>(R.k + (size_t)s * R.ldkv + lane * 4);
    float2 k0 = __half22float2(*reinterpret_cast<__half2*>(&kraw.x));
    float2 k1 = __half22float2(*reinterpret_cast<__half2*>(&kraw.y));
    float acc = q0.x * k0.x + q0.y * k0.y + q1.x * k1.x + q1.y * k1.y;
    acc += __shfl_xor_sync(0xffffffffu, acc, 1);
    acc += __shfl_xor_sync(0xffffffffu, acc, 2);
    acc += __shfl_xor_sync(0xffffffffu, acc, 4);
    int h = lane >> 3;
    float a = acc * __ldg(&R.prel[h]) * 0.17677669529663689f; // 1/sqrt(32)
    float ex = expf(a);
    uint2 vraw = *reinterpret_cast<const uint2*>(R.v + (size_t)s * R.ldkv + lane * 4);
    float2 v0 = __half22float2(*reinterpret_cast<__half2*>(&vraw.x));
    float2 v1 = __half22float2(*reinterpret_cast<__half2*>(&vraw.y));
    float* p = R.aggr + (size_t)d * HID + lane * 4;
    asm volatile("red.global.add.v4.f32 [%0], {%1,%2,%3,%4};"
                 :: "l"(p), "f"(v0.x * ex), "f"(v0.y * ex),
                    "f"(v1.x * ex), "f"(v1.y * ex)
                 : "memory");
    if ((lane & 7) == 0)
        atomicAdd(&R.ssum[(size_t)d * NH + h], ex);
}

// ---------------------------------------------------------------------------
// Combiner: normalize per-relation aggregates, sum, gelu.
// ---------------------------------------------------------------------------
__global__ void combine_k(const float* __restrict__ aggr,
                          const float* __restrict__ ssum,
                          float* __restrict__ agg)
{
    int idx = blockIdx.x * blockDim.x + threadIdx.x;
    int total = (N0 + N1) * (HID / 4);
    if (idx >= total) return;
    int n = idx >> 5;
    int c4 = idx & 31;
    int h = c4 >> 3;
    float4 o;
    if (n < N0) {
        const float* ar = aggr + (size_t)N1 * HID;
        float inv = 1.f / (ssum[(size_t)N0 * NH * 1 + (size_t)n * NH + h] + 1e-16f);
        float4 v = reinterpret_cast<const float4*>(ar + (size_t)n * HID)[c4];
        o = make_float4(v.x * inv, v.y * inv, v.z * inv, v.w * inv);
    } else {
        int m = n - N0;
        const float* ar0 = aggr;
        const float* ar2 = aggr + (size_t)(N1 + N0) * HID;
        float inv0 = 1.f / (ssum[(size_t)m * NH + h] + 1e-16f);
        float inv2 = 1.f / (ssum[(size_t)N0 * NH * 2 + (size_t)m * NH + h] + 1e-16f);
        float4 v0 = reinterpret_cast<const float4*>(ar0 + (size_t)m * HID)[c4];
        float4 v2 = reinterpret_cast<const float4*>(ar2 + (size_t)m * HID)[c4];
        o = make_float4(v0.x * inv0 + v2.x * inv2, v0.y * inv0 + v2.y * inv2,
                        v0.z * inv0 + v2.z * inv2, v0.w * inv0 + v2.w * inv2);
    }
    o.x = gelu_exact(o.x);
    o.y = gelu_exact(o.y);
    o.z = gelu_exact(o.z);
    o.w = gelu_exact(o.w);
    reinterpret_cast<float4*>(agg + (size_t)n * HID)[c4] = o;
}

// ---------------------------------------------------------------------------
// Host orchestration
// ---------------------------------------------------------------------------
extern "C" void kernel_launch(void* const* d_in, const int* in_sizes, int n_in,
                              void* d_out, int out_size)
{
    const float* x0   = (const float*)d_in[0];
    const float* x1   = (const float*)d_in[1];
    const int* srcp[3] = {(const int*)d_in[2], (const int*)d_in[4], (const int*)d_in[6]};
    const int* dstp[3] = {(const int*)d_in[3], (const int*)d_in[5], (const int*)d_in[7]};
    const int  Ecnt[3] = {in_sizes[2], in_sizes[4], in_sizes[6]};
    const float* W_in = (const float*)d_in[8];
    const float* b_in = (const float*)d_in[9];
    const float* Wk   = (const float*)d_in[10];
    const float* bk   = (const float*)d_in[11];
    const float* Wq   = (const float*)d_in[12];
    const float* bq   = (const float*)d_in[13];
    const float* Wv   = (const float*)d_in[14];
    const float* bv   = (const float*)d_in[15];
    const float* Wa   = (const float*)d_in[16];
    const float* ba   = (const float*)d_in[17];
    const float* skip = (const float*)d_in[18];
    const float* a_rel = (const float*)d_in[19];
    const float* m_rel = (const float*)d_in[20];
    const float* p_rel = (const float*)d_in[21];

    float* out = (float*)d_out;
    const int OW = HID * (NL + 1);       // 384
    float* y0 = out;
    float* y1 = out + (size_t)N0 * OW;

    float *agg, *aggr, *bcat0, *bcat1;
    __half *q0, *q1, *kv0, *kv1, *wcat0, *wcat1, *win, *wa;
    cudaGetSymbolAddress((void**)&q0,    g_q0);
    cudaGetSymbolAddress((void**)&q1,    g_q1);
    cudaGetSymbolAddress((void**)&kv0,   g_kv0);
    cudaGetSymbolAddress((void**)&kv1,   g_kv1);
    cudaGetSymbolAddress((void**)&agg,   g_agg);
    cudaGetSymbolAddress((void**)&aggr,  g_aggr);
    cudaGetSymbolAddress((void**)&wcat0, g_wcat0);
    cudaGetSymbolAddress((void**)&wcat1, g_wcat1);
    cudaGetSymbolAddress((void**)&bcat0, g_bcat0);
    cudaGetSymbolAddress((void**)&bcat1, g_bcat1);
    cudaGetSymbolAddress((void**)&win,   g_win);
    cudaGetSymbolAddress((void**)&wa,    g_wa);
    float* ssum = aggr + AGGR_FLOATS;

    cudaFuncSetAttribute(gemm_tc<0,1>, cudaFuncAttributeMaxDynamicSharedMemorySize, GEMM_SMEM);
    cudaFuncSetAttribute(gemm_tc<1,0>, cudaFuncAttributeMaxDynamicSharedMemorySize, GEMM_SMEM);
    cudaFuncSetAttribute(gemm_tc<2,0>, cudaFuncAttributeMaxDynamicSharedMemorySize, GEMM_SMEM);

    // ---- ALL weight prep in one launch (22 sections, transposed fp16)
    {
        WPrepN P;
        P.s[0] = {W_in,             b_in, nullptr, win,             nullptr};
        P.s[1] = {W_in + HID * HID, b_in, nullptr, win + HID * HID, nullptr};
        for (int l = 0; l < NL; l++) {
            __half* wc0 = wcat0 + (size_t)l * HID * LD0;
            __half* wc1 = wcat1 + (size_t)l * HID * LD1;
            float* bc0 = bcat0 + (size_t)l * LD0;
            float* bc1 = bcat1 + (size_t)l * LD1;
            __half* wal = wa + (size_t)l * 2 * HID * HID;
            const float* WkL0 = Wk + (size_t)(l * 2 + 0) * HID * HID;
            const float* WkL1 = Wk + (size_t)(l * 2 + 1) * HID * HID;
            const float* WvL0 = Wv + (size_t)(l * 2 + 0) * HID * HID;
            const float* WvL1 = Wv + (size_t)(l * 2 + 1) * HID * HID;
            const float* ar0 = a_rel + (size_t)(l * 3 + 0) * NH * HD * HD;
            const float* ar1 = a_rel + (size_t)(l * 3 + 1) * NH * HD * HD;
            const float* ar2 = a_rel + (size_t)(l * 3 + 2) * NH * HD * HD;
            const float* mr0 = m_rel + (size_t)(l * 3 + 0) * NH * HD * HD;
            const float* mr1 = m_rel + (size_t)(l * 3 + 1) * NH * HD * HD;
            const float* mr2 = m_rel + (size_t)(l * 3 + 2) * NH * HD * HD;
            int o = 2 + l * 10;
            // transposed section offsets: section s at wc + s*HID*HID (n-major)
            P.s[o + 0] = {Wq + (size_t)(l*2+0)*HID*HID, bq + (l*2+0)*HID, nullptr, wc0,                 bc0};
            P.s[o + 1] = {WkL0, bk + (l*2+0)*HID, ar0, wc0 + 1 * HID * HID, bc0 + 128};
            P.s[o + 2] = {WvL0, bv + (l*2+0)*HID, mr0, wc0 + 2 * HID * HID, bc0 + 256};
            P.s[o + 3] = {Wq + (size_t)(l*2+1)*HID*HID, bq + (l*2+1)*HID, nullptr, wc1,                 bc1};
            P.s[o + 4] = {WkL1, bk + (l*2+1)*HID, ar1, wc1 + 1 * HID * HID, bc1 + 128};
            P.s[o + 5] = {WvL1, bv + (l*2+1)*HID, mr1, wc1 + 2 * HID * HID, bc1 + 256};
            P.s[o + 6] = {WkL1, bk + (l*2+1)*HID, ar2, wc1 + 3 * HID * HID, bc1 + 384};
            P.s[o + 7] = {WvL1, bv + (l*2+1)*HID, mr2, wc1 + 4 * HID * HID, bc1 + 512};
            P.s[o + 8] = {Wa + (size_t)(l*2+0)*HID*HID, nullptr, nullptr, wal,             nullptr};
            P.s[o + 9] = {Wa + (size_t)(l*2+1)*HID*HID, nullptr, nullptr, wal + HID * HID, nullptr};
        }
        prep_w_k<<<dim3(HID + 1, 22), HID>>>(P);
    }

    // ---- input projection (both types, one launch)
    {
        GemmPair P;
        P.nb0 = NB0;
        P.s[0] = {x0, HID, win,             b_in,       y0, OW, nullptr, nullptr, 0, N0, 1, nullptr, 0, nullptr};
        P.s[1] = {x1, HID, win + HID * HID, b_in + HID, y1, OW, nullptr, nullptr, 0, N1, 1, nullptr, 0, nullptr};
        gemm_tc<1,0><<<dim3(NB0 + NB1, 1), 512, GEMM_SMEM>>>(P);
    }

    for (int l = 0; l < NL; l++) {
        const float* h0 = y0 + l * HID;  // lda = OW
        const float* h1 = y1 + l * HID;
        const __half* wc0 = wcat0 + (size_t)l * HID * LD0;
        const __half* wc1 = wcat1 + (size_t)l * HID * LD1;
        const float* bc0 = bcat0 + (size_t)l * LD0;
        const float* bc1 = bcat1 + (size_t)l * LD1;
        const __half* wal = wa + (size_t)l * 2 * HID * HID;

        // ---- fused qkv projections: all sections -> fp16
        {
            GemmPair P;
            P.nb0 = NB0;
            P.s[0] = {h0, OW, wc0, bc0, nullptr, 0, q0, kv0, KV0, N0, LD0 / GBN, nullptr, 0, nullptr};
            P.s[1] = {h1, OW, wc1, bc1, nullptr, 0, q1, kv1, KV1, N1, LD1 / GBN, nullptr, 0, nullptr};
            gemm_tc<0,1><<<dim3(NB0 + NB1, LD1 / GBN), 512, GEMM_SMEM>>>(P);
        }

        // one memset covers aggr + ssum (contiguous)
        cudaMemsetAsync(aggr, 0, (AGGR_FLOATS + SSUM_FLOATS) * sizeof(float), 0);

        // ---- single-pass fused edge stage (all fp16 gathers)
        Edge3 EP;
        float* aggr_tab[3] = {aggr,
                              aggr + (size_t)N1 * HID,
                              aggr + (size_t)(N1 + N0) * HID};
        EP.r[0] = {srcp[0], dstp[0], q1, kv0, kv0 + 128, KV0,
                   p_rel + (size_t)(l * 3 + 0) * NH, ssum, aggr_tab[0]};
        EP.r[1] = {srcp[1], dstp[1], q0, kv1, kv1 + 128, KV1,
                   p_rel + (size_t)(l * 3 + 1) * NH, ssum + (size_t)N0 * NH, aggr_tab[1]};
        EP.r[2] = {srcp[2], dstp[2], q1, kv1 + 256, kv1 + 384, KV1,
                   p_rel + (size_t)(l * 3 + 2) * NH, ssum + (size_t)2 * N0 * NH, aggr_tab[2]};
        EP.off1 = Ecnt[0];
        EP.off2 = Ecnt[0] + Ecnt[1];
        EP.total = Ecnt[0] + Ecnt[1] + Ecnt[2];
        int eBlocks = (EP.total + 7) / 8;
        edge_fused_k<<<eBlocks, 256>>>(EP);

        // ---- combine + gelu
        int cThreads = (N0 + N1) * (HID / 4);
        combine_k<<<(cThreads + 255) / 256, 256>>>(aggr, ssum, agg);

        // ---- output projection + skip blend (both types, one launch)
        {
            GemmPair P;
            P.nb0 = NB0;
            P.s[0] = {agg, HID, wal, ba + (l * 2 + 0) * HID,
                      y0 + (l + 1) * HID, OW, nullptr, nullptr, 0, N0, 1, h0, OW, skip + l * 2 + 0};
            P.s[1] = {agg + (size_t)N0 * HID, HID, wal + HID * HID,
                      ba + (l * 2 + 1) * HID,
                      y1 + (l + 1) * HID, OW, nullptr, nullptr, 0, N1, 1, h1, OW, skip + l * 2 + 1};
            gemm_tc<2,0><<<dim3(NB0 + NB1, 1), 512, GEMM_SMEM>>>(P);
        }
    }
}

// round 17
// speedup vs baseline: 1.1259x; 1.1259x over previous
#include <cuda_runtime.h>
#include <cuda_fp16.h>
#include <math.h>
#include <stdint.h>

// ---------------------------------------------------------------------------
// Problem constants
// ---------------------------------------------------------------------------
#define N0 100000
#define N1 50000
#define HID 128
#define NH 4
#define HD 32
#define NL 2

#define LD0 384
#define LD1 640
#define KV0 256   // halves per type0 kv row (k@0, v@128)
#define KV1 512   // halves per type1 kv row (k1@0, v1@128, k2@256, v2@384)

#define NB0 ((N0 + 127) / 128)
#define NB1 ((N1 + 127) / 128)

#define AGGR_FLOATS ((size_t)(N0 + 2 * N1) * HID)
#define SSUM_FLOATS ((size_t)3 * N0 * NH)

// ---------------------------------------------------------------------------
// Static device scratch
// ---------------------------------------------------------------------------
__device__ __half g_q0[(size_t)N0 * HID];
__device__ __half g_q1[(size_t)N1 * HID];
__device__ __half g_kv0[(size_t)N0 * KV0];
__device__ __half g_kv1[(size_t)N1 * KV1];
__device__ __half g_h0[(size_t)N0 * HID];     // fp16 mirror of current h (type0)
__device__ __half g_h1[(size_t)N1 * HID];
__device__ __half g_aggh[(size_t)(N0 + N1) * HID];  // fp16 gelu(combined agg)
__device__ float  g_aggr[AGGR_FLOATS + SSUM_FLOATS];
__device__ __half g_wcat0[NL * HID * LD0];    // transposed [n][k] fp16
__device__ __half g_wcat1[NL * HID * LD1];
__device__ float  g_bcat0[NL * LD0];
__device__ float  g_bcat1[NL * LD1];
__device__ __half g_win[2 * HID * HID];       // transposed fp16
__device__ __half g_wa[NL * 2 * HID * HID];   // transposed fp16

// ---------------------------------------------------------------------------
// Helpers
// ---------------------------------------------------------------------------
__device__ __forceinline__ float gelu_exact(float x) {
    return 0.5f * x * (1.0f + erff(x * 0.7071067811865476f));
}
__device__ __forceinline__ unsigned pack_h2(float a, float b) {
    __half2 h = __floats2half2_rn(a, b);
    return *reinterpret_cast<unsigned*>(&h);
}
__device__ __forceinline__ void mma_f16(float* c, const unsigned* a, const unsigned* b) {
    asm("mma.sync.aligned.m16n8k16.row.col.f32.f16.f16.f32 "
        "{%0,%1,%2,%3}, {%4,%5,%6,%7}, {%8,%9}, {%0,%1,%2,%3};"
        : "+f"(c[0]), "+f"(c[1]), "+f"(c[2]), "+f"(c[3])
        : "r"(a[0]), "r"(a[1]), "r"(a[2]), "r"(a[3]), "r"(b[0]), "r"(b[1]));
}
__device__ __forceinline__ void cpa16f(float* dst, const float* src) {
    unsigned d = (unsigned)__cvta_generic_to_shared(dst);
    asm volatile("cp.async.cg.shared.global [%0], [%1], 16;" :: "r"(d), "l"(src));
}
__device__ __forceinline__ void cpa16h(__half* dst, const __half* src) {
    unsigned d = (unsigned)__cvta_generic_to_shared(dst);
    asm volatile("cp.async.cg.shared.global [%0], [%1], 16;" :: "r"(d), "l"(src));
}
__device__ __forceinline__ void cp_commit() { asm volatile("cp.async.commit_group;"); }
template <int N>
__device__ __forceinline__ void cp_wait() {
    asm volatile("cp.async.wait_group %0;" :: "n"(N));
}

// ---------------------------------------------------------------------------
// Paired FP16 TC GEMM (m16n8k16, fp32 accum). 128x128x16, 512 threads.
//   AHALF=1: A fp16 (smem halves, ld 24, direct half2 fragments)
//   AHALF=0: A fp32 (smem floats, ld 20, convert at fragment load)
//   EPI: 0 none, 1 relu, 2 skip-blend
//   OUTH=1: fp16 outputs (y==0 -> Cq, y>=1 -> Ckv at col-128)
//   MIR=1:  fp32 C write + fp16 mirror into Cq (ld HID)
// ---------------------------------------------------------------------------
#define GBM 128
#define GBN 128
#define AF_LD 20                   // floats, fp32-A variant
#define AH_LD 24                   // halves, fp16-A variant
#define BS_LD 24                   // halves
#define A_STG_B 10240              // bytes reserved per A stage (max of both)
#define B_STG_B 6144               // bytes per B stage
#define GEMM_SMEM (3 * (A_STG_B + B_STG_B))

struct GemmSide {
    const float*  A; int lda;      // fp32 A (AHALF=0)
    const __half* Ah;              // fp16 A, ld HID (AHALF=1)
    const __half* B;               // [n_total][128] fp16
    const float* bias;
    float* C; int ldc;
    __half* Cq;                    // q out (OUTH) or fp16 mirror (MIR)
    __half* Ckv; int ldkv;
    int M; int nby;
    const float* hprev; int ldh;
    const float* skipPtr;
};
struct GemmPair { GemmSide s[2]; int nb0; };

template <int EPI, int AHALF, int OUTH, int MIR>
__global__ __launch_bounds__(512, 2) void gemm_tc(GemmPair P)
{
    extern __shared__ char smc[];

    const int side = (blockIdx.x >= (unsigned)P.nb0);
    const GemmSide S = P.s[side];
    const int bx = side ? (blockIdx.x - P.nb0) : blockIdx.x;
    if ((int)blockIdx.y >= S.nby) return;

    const int tid  = threadIdx.x;
    const int wid  = tid >> 5;
    const int lane = tid & 31;
    const int row0 = bx * GBM;
    const int col0 = blockIdx.y * GBN;
    const int wm0  = (wid >> 2) * 32;
    const int wn0  = (wid & 3) * 32;
    const int g    = lane >> 2;
    const int tig  = lane & 3;

    // loader coordinates
    const int rAf = tid >> 2, kcAf = (tid & 3) << 2;      // fp32 A: 16B/thread
    int gArowF = row0 + rAf; if (gArowF >= S.M) gArowF = S.M - 1;
    const int rAh = (tid & 255) >> 1, kcAh = (tid & 1) << 3; // fp16 A: 16B, tid<256
    int gArowH = row0 + rAh; if (gArowH >= S.M) gArowH = S.M - 1;
    const int nB2 = (tid & 255) >> 1, koB2 = (tid & 1) << 3; // B: 16B, half threads

    auto stage_load = [&](int s, int kt) {
        __half* Bs = reinterpret_cast<__half*>(smc + 3 * A_STG_B + s * B_STG_B);
        if (AHALF) {
            if (tid < 256) {
                __half* As = reinterpret_cast<__half*>(smc + s * A_STG_B);
                cpa16h(As + rAh * AH_LD + kcAh,
                       S.Ah + (size_t)gArowH * HID + kt * 16 + kcAh);
            } else {
                cpa16h(Bs + nB2 * BS_LD + koB2,
                       S.B + (size_t)(col0 + nB2) * HID + kt * 16 + koB2);
            }
        } else {
            float* As = reinterpret_cast<float*>(smc + s * A_STG_B);
            cpa16f(As + rAf * AF_LD + kcAf,
                   S.A + (size_t)gArowF * S.lda + kt * 16 + kcAf);
            if (tid < 256)
                cpa16h(Bs + nB2 * BS_LD + koB2,
                       S.B + (size_t)(col0 + nB2) * HID + kt * 16 + koB2);
        }
    };

    stage_load(0, 0); cp_commit();
    stage_load(1, 1); cp_commit();

    float acc[2][4][4];
#pragma unroll
    for (int i = 0; i < 2; i++)
#pragma unroll
        for (int j = 0; j < 4; j++)
#pragma unroll
            for (int q = 0; q < 4; q++) acc[i][j][q] = 0.f;

#pragma unroll
    for (int kt = 0; kt < 8; kt++) {
        cp_wait<1>();
        __syncthreads();
        if (kt + 2 < 8) stage_load((kt + 2) % 3, kt + 2);
        cp_commit();

        const __half* Bst = reinterpret_cast<const __half*>(
            smc + 3 * A_STG_B + (kt % 3) * B_STG_B);

        unsigned aR[2][4], bR[4][2];
        if (AHALF) {
            const __half* Ast = reinterpret_cast<const __half*>(smc + (kt % 3) * A_STG_B);
#pragma unroll
            for (int mt = 0; mt < 2; mt++) {
                int m = wm0 + mt * 16 + g;
                aR[mt][0] = *reinterpret_cast<const unsigned*>(&Ast[(size_t)m * AH_LD + 2 * tig]);
                aR[mt][1] = *reinterpret_cast<const unsigned*>(&Ast[(size_t)(m + 8) * AH_LD + 2 * tig]);
                aR[mt][2] = *reinterpret_cast<const unsigned*>(&Ast[(size_t)m * AH_LD + 2 * tig + 8]);
                aR[mt][3] = *reinterpret_cast<const unsigned*>(&Ast[(size_t)(m + 8) * AH_LD + 2 * tig + 8]);
            }
        } else {
            const float* Ast = reinterpret_cast<const float*>(smc + (kt % 3) * A_STG_B);
#pragma unroll
            for (int mt = 0; mt < 2; mt++) {
                int m = wm0 + mt * 16 + g;
                float2 f0 = *reinterpret_cast<const float2*>(&Ast[(size_t)m * AF_LD + 2 * tig]);
                float2 f2 = *reinterpret_cast<const float2*>(&Ast[(size_t)m * AF_LD + 2 * tig + 8]);
                float2 f1 = *reinterpret_cast<const float2*>(&Ast[(size_t)(m + 8) * AF_LD + 2 * tig]);
                float2 f3 = *reinterpret_cast<const float2*>(&Ast[(size_t)(m + 8) * AF_LD + 2 * tig + 8]);
                aR[mt][0] = pack_h2(f0.x, f0.y);
                aR[mt][1] = pack_h2(f1.x, f1.y);
                aR[mt][2] = pack_h2(f2.x, f2.y);
                aR[mt][3] = pack_h2(f3.x, f3.y);
            }
        }
#pragma unroll
        for (int nt = 0; nt < 4; nt++) {
            int n = wn0 + nt * 8 + g;
            bR[nt][0] = *reinterpret_cast<const unsigned*>(&Bst[(size_t)n * BS_LD + 2 * tig]);
            bR[nt][1] = *reinterpret_cast<const unsigned*>(&Bst[(size_t)n * BS_LD + 2 * tig + 8]);
        }
#pragma unroll
        for (int mt = 0; mt < 2; mt++)
#pragma unroll
            for (int nt = 0; nt < 4; nt++)
                mma_f16(acc[mt][nt], aR[mt], bR[nt]);
    }

    float sgate = 0.f;
    if (EPI == 2) sgate = 1.f / (1.f + expf(-(*S.skipPtr)));

#pragma unroll
    for (int mt = 0; mt < 2; mt++) {
#pragma unroll
        for (int rr = 0; rr < 2; rr++) {
            int grow = row0 + wm0 + mt * 16 + g + rr * 8;
            if (grow >= S.M) continue;
#pragma unroll
            for (int nt = 0; nt < 4; nt++) {
                int col = col0 + wn0 + nt * 8 + 2 * tig;
                float v0 = acc[mt][nt][rr * 2 + 0] + S.bias[col];
                float v1 = acc[mt][nt][rr * 2 + 1] + S.bias[col + 1];
                if (EPI == 1) { v0 = fmaxf(v0, 0.f); v1 = fmaxf(v1, 0.f); }
                if (EPI == 2) {
                    const float* hp = S.hprev + (size_t)grow * S.ldh + col;
                    v0 = sgate * v0 + (1.f - sgate) * hp[0];
                    v1 = sgate * v1 + (1.f - sgate) * hp[1];
                }
                if (OUTH == 1) {
                    __half2 hv = __floats2half2_rn(v0, v1);
                    if (blockIdx.y == 0)
                        *reinterpret_cast<__half2*>(S.Cq + (size_t)grow * HID + col) = hv;
                    else
                        *reinterpret_cast<__half2*>(
                            S.Ckv + (size_t)grow * S.ldkv + (col - 128)) = hv;
                } else {
                    *reinterpret_cast<float2*>(S.C + (size_t)grow * S.ldc + col) =
                        make_float2(v0, v1);
                    if (MIR)
                        *reinterpret_cast<__half2*>(S.Cq + (size_t)grow * HID + col) =
                            __floats2half2_rn(v0, v1);
                }
            }
        }
    }
}

// ---------------------------------------------------------------------------
// Weight prep: 22 sections, outputs TRANSPOSED fp16 [n][k]. A==nullptr -> copy.
// ---------------------------------------------------------------------------
struct WPrepSec {
    const float* W; const float* b; const float* A;
    __half* Wd; float* bd;
};
struct WPrepN { WPrepSec s[22]; };

__global__ void prep_w_k(WPrepN P)
{
    WPrepSec p = P.s[blockIdx.y];
    int col = threadIdx.x;
    int i = blockIdx.x;
    if (p.A == nullptr) {
        if (i < HID)
            p.Wd[(size_t)col * HID + i] = __float2half(p.W[(size_t)i * HID + col]);
        else if (p.bd) p.bd[col] = p.b[col];
        return;
    }
    int h = col >> 5, e = col & 31;
    const float* Ah = p.A + h * HD * HD;
    if (i < HID) {
        const float* wrow = p.W + (size_t)i * HID + h * HD;
        float acc = 0.f;
#pragma unroll
        for (int d = 0; d < HD; d++) acc = fmaf(wrow[d], Ah[d * HD + e], acc);
        p.Wd[(size_t)col * HID + i] = __float2half(acc);
    } else if (p.bd) {
        const float* brow = p.b + h * HD;
        float acc = 0.f;
#pragma unroll
        for (int d = 0; d < HD; d++) acc = fmaf(brow[d], Ah[d * HD + e], acc);
        p.bd[col] = acc;
    }
}

// ---------------------------------------------------------------------------
// Single-pass fused edge kernel (warp per edge). q, k, v all fp16.
// ---------------------------------------------------------------------------
struct EdgeRel {
    const int* src; const int* dst;
    const __half* q;
    const __half* k; const __half* v; int ldkv;
    const float* prel;
    float* ssum; float* aggr;
};
struct Edge3 { EdgeRel r[3]; int off1, off2, total; };

__global__ void edge_fused_k(Edge3 P)
{
    int w = blockIdx.x * (blockDim.x >> 5) + (threadIdx.x >> 5);
    if (w >= P.total) return;
    int lane = threadIdx.x & 31;
    int ri = (w >= P.off1) + (w >= P.off2);
    int base = ri == 0 ? 0 : (ri == 1 ? P.off1 : P.off2);
    EdgeRel R = P.r[ri];
    int e = w - base;
    int s = __ldg(&R.src[e]), d = __ldg(&R.dst[e]);
    uint2 qraw = *reinterpret_cast<const uint2*>(R.q + (size_t)d * HID + lane * 4);
    float2 q0 = __half22float2(*reinterpret_cast<__half2*>(&qraw.x));
    float2 q1 = __half22float2(*reinterpret_cast<__half2*>(&qraw.y));
    uint2 kraw = *reinterpret_cast<const uint2*>(R.k + (size_t)s * R.ldkv + lane * 4);
    float2 k0 = __half22float2(*reinterpret_cast<__half2*>(&kraw.x));
    float2 k1 = __half22float2(*reinterpret_cast<__half2*>(&kraw.y));
    float acc = q0.x * k0.x + q0.y * k0.y + q1.x * k1.x + q1.y * k1.y;
    acc += __shfl_xor_sync(0xffffffffu, acc, 1);
    acc += __shfl_xor_sync(0xffffffffu, acc, 2);
    acc += __shfl_xor_sync(0xffffffffu, acc, 4);
    int h = lane >> 3;
    float a = acc * __ldg(&R.prel[h]) * 0.17677669529663689f; // 1/sqrt(32)
    float ex = expf(a);
    uint2 vraw = *reinterpret_cast<const uint2*>(R.v + (size_t)s * R.ldkv + lane * 4);
    float2 v0 = __half22float2(*reinterpret_cast<__half2*>(&vraw.x));
    float2 v1 = __half22float2(*reinterpret_cast<__half2*>(&vraw.y));
    float* p = R.aggr + (size_t)d * HID + lane * 4;
    asm volatile("red.global.add.v4.f32 [%0], {%1,%2,%3,%4};"
                 :: "l"(p), "f"(v0.x * ex), "f"(v0.y * ex),
                    "f"(v1.x * ex), "f"(v1.y * ex)
                 : "memory");
    if ((lane & 7) == 0)
        atomicAdd(&R.ssum[(size_t)d * NH + h], ex);
}

// ---------------------------------------------------------------------------
// Combiner: normalize per-relation aggregates, sum, gelu -> fp16 agg.
// ---------------------------------------------------------------------------
__global__ void combine_k(const float* __restrict__ aggr,
                          const float* __restrict__ ssum,
                          __half* __restrict__ aggh)
{
    int idx = blockIdx.x * blockDim.x + threadIdx.x;
    int total = (N0 + N1) * (HID / 4);
    if (idx >= total) return;
    int n = idx >> 5;
    int c4 = idx & 31;
    int h = c4 >> 3;
    float4 o;
    if (n < N0) {
        const float* ar = aggr + (size_t)N1 * HID;
        float inv = 1.f / (ssum[(size_t)N0 * NH * 1 + (size_t)n * NH + h] + 1e-16f);
        float4 v = reinterpret_cast<const float4*>(ar + (size_t)n * HID)[c4];
        o = make_float4(v.x * inv, v.y * inv, v.z * inv, v.w * inv);
    } else {
        int m = n - N0;
        const float* ar0 = aggr;
        const float* ar2 = aggr + (size_t)(N1 + N0) * HID;
        float inv0 = 1.f / (ssum[(size_t)m * NH + h] + 1e-16f);
        float inv2 = 1.f / (ssum[(size_t)N0 * NH * 2 + (size_t)m * NH + h] + 1e-16f);
        float4 v0 = reinterpret_cast<const float4*>(ar0 + (size_t)m * HID)[c4];
        float4 v2 = reinterpret_cast<const float4*>(ar2 + (size_t)m * HID)[c4];
        o = make_float4(v0.x * inv0 + v2.x * inv2, v0.y * inv0 + v2.y * inv2,
                        v0.z * inv0 + v2.z * inv2, v0.w * inv0 + v2.w * inv2);
    }
    __half2 h0 = __floats2half2_rn(gelu_exact(o.x), gelu_exact(o.y));
    __half2 h1 = __floats2half2_rn(gelu_exact(o.z), gelu_exact(o.w));
    uint2 pk = make_uint2(*reinterpret_cast<unsigned*>(&h0),
                          *reinterpret_cast<unsigned*>(&h1));
    reinterpret_cast<uint2*>(aggh + (size_t)n * HID)[c4] = pk;
}

// ---------------------------------------------------------------------------
// Host orchestration
// ---------------------------------------------------------------------------
extern "C" void kernel_launch(void* const* d_in, const int* in_sizes, int n_in,
                              void* d_out, int out_size)
{
    const float* x0   = (const float*)d_in[0];
    const float* x1   = (const float*)d_in[1];
    const int* srcp[3] = {(const int*)d_in[2], (const int*)d_in[4], (const int*)d_in[6]};
    const int* dstp[3] = {(const int*)d_in[3], (const int*)d_in[5], (const int*)d_in[7]};
    const int  Ecnt[3] = {in_sizes[2], in_sizes[4], in_sizes[6]};
    const float* W_in = (const float*)d_in[8];
    const float* b_in = (const float*)d_in[9];
    const float* Wk   = (const float*)d_in[10];
    const float* bk   = (const float*)d_in[11];
    const float* Wq   = (const float*)d_in[12];
    const float* bq   = (const float*)d_in[13];
    const float* Wv   = (const float*)d_in[14];
    const float* bv   = (const float*)d_in[15];
    const float* Wa   = (const float*)d_in[16];
    const float* ba   = (const float*)d_in[17];
    const float* skip = (const float*)d_in[18];
    const float* a_rel = (const float*)d_in[19];
    const float* m_rel = (const float*)d_in[20];
    const float* p_rel = (const float*)d_in[21];

    float* out = (float*)d_out;
    const int OW = HID * (NL + 1);       // 384
    float* y0 = out;
    float* y1 = out + (size_t)N0 * OW;

    float *aggr, *bcat0, *bcat1;
    __half *q0, *q1, *kv0, *kv1, *h0h, *h1h, *aggh, *wcat0, *wcat1, *win, *wa;
    cudaGetSymbolAddress((void**)&q0,    g_q0);
    cudaGetSymbolAddress((void**)&q1,    g_q1);
    cudaGetSymbolAddress((void**)&kv0,   g_kv0);
    cudaGetSymbolAddress((void**)&kv1,   g_kv1);
    cudaGetSymbolAddress((void**)&h0h,   g_h0);
    cudaGetSymbolAddress((void**)&h1h,   g_h1);
    cudaGetSymbolAddress((void**)&aggh,  g_aggh);
    cudaGetSymbolAddress((void**)&aggr,  g_aggr);
    cudaGetSymbolAddress((void**)&wcat0, g_wcat0);
    cudaGetSymbolAddress((void**)&wcat1, g_wcat1);
    cudaGetSymbolAddress((void**)&bcat0, g_bcat0);
    cudaGetSymbolAddress((void**)&bcat1, g_bcat1);
    cudaGetSymbolAddress((void**)&win,   g_win);
    cudaGetSymbolAddress((void**)&wa,    g_wa);
    float* ssum = aggr + AGGR_FLOATS;

    cudaFuncSetAttribute(gemm_tc<1,0,0,1>, cudaFuncAttributeMaxDynamicSharedMemorySize, GEMM_SMEM);
    cudaFuncSetAttribute(gemm_tc<0,1,1,0>, cudaFuncAttributeMaxDynamicSharedMemorySize, GEMM_SMEM);
    cudaFuncSetAttribute(gemm_tc<2,1,0,1>, cudaFuncAttributeMaxDynamicSharedMemorySize, GEMM_SMEM);

    // ---- ALL weight prep in one launch (22 sections, transposed fp16)
    {
        WPrepN P;
        P.s[0] = {W_in,             b_in, nullptr, win,             nullptr};
        P.s[1] = {W_in + HID * HID, b_in, nullptr, win + HID * HID, nullptr};
        for (int l = 0; l < NL; l++) {
            __half* wc0 = wcat0 + (size_t)l * HID * LD0;
            __half* wc1 = wcat1 + (size_t)l * HID * LD1;
            float* bc0 = bcat0 + (size_t)l * LD0;
            float* bc1 = bcat1 + (size_t)l * LD1;
            __half* wal = wa + (size_t)l * 2 * HID * HID;
            const float* WkL0 = Wk + (size_t)(l * 2 + 0) * HID * HID;
            const float* WkL1 = Wk + (size_t)(l * 2 + 1) * HID * HID;
            const float* WvL0 = Wv + (size_t)(l * 2 + 0) * HID * HID;
            const float* WvL1 = Wv + (size_t)(l * 2 + 1) * HID * HID;
            const float* ar0 = a_rel + (size_t)(l * 3 + 0) * NH * HD * HD;
            const float* ar1 = a_rel + (size_t)(l * 3 + 1) * NH * HD * HD;
            const float* ar2 = a_rel + (size_t)(l * 3 + 2) * NH * HD * HD;
            const float* mr0 = m_rel + (size_t)(l * 3 + 0) * NH * HD * HD;
            const float* mr1 = m_rel + (size_t)(l * 3 + 1) * NH * HD * HD;
            const float* mr2 = m_rel + (size_t)(l * 3 + 2) * NH * HD * HD;
            int o = 2 + l * 10;
            P.s[o + 0] = {Wq + (size_t)(l*2+0)*HID*HID, bq + (l*2+0)*HID, nullptr, wc0,                 bc0};
            P.s[o + 1] = {WkL0, bk + (l*2+0)*HID, ar0, wc0 + 1 * HID * HID, bc0 + 128};
            P.s[o + 2] = {WvL0, bv + (l*2+0)*HID, mr0, wc0 + 2 * HID * HID, bc0 + 256};
            P.s[o + 3] = {Wq + (size_t)(l*2+1)*HID*HID, bq + (l*2+1)*HID, nullptr, wc1,                 bc1};
            P.s[o + 4] = {WkL1, bk + (l*2+1)*HID, ar1, wc1 + 1 * HID * HID, bc1 + 128};
            P.s[o + 5] = {WvL1, bv + (l*2+1)*HID, mr1, wc1 + 2 * HID * HID, bc1 + 256};
            P.s[o + 6] = {WkL1, bk + (l*2+1)*HID, ar2, wc1 + 3 * HID * HID, bc1 + 384};
            P.s[o + 7] = {WvL1, bv + (l*2+1)*HID, mr2, wc1 + 4 * HID * HID, bc1 + 512};
            P.s[o + 8] = {Wa + (size_t)(l*2+0)*HID*HID, nullptr, nullptr, wal,             nullptr};
            P.s[o + 9] = {Wa + (size_t)(l*2+1)*HID*HID, nullptr, nullptr, wal + HID * HID, nullptr};
        }
        prep_w_k<<<dim3(HID + 1, 22), HID>>>(P);
    }

    // ---- input projection (fp32 A path; writes y fp32 + fp16 mirror)
    {
        GemmPair P;
        P.nb0 = NB0;
        P.s[0] = {x0, HID, nullptr, win,             b_in,       y0, OW, h0h, nullptr, 0, N0, 1, nullptr, 0, nullptr};
        P.s[1] = {x1, HID, nullptr, win + HID * HID, b_in + HID, y1, OW, h1h, nullptr, 0, N1, 1, nullptr, 0, nullptr};
        gemm_tc<1,0,0,1><<<dim3(NB0 + NB1, 1), 512, GEMM_SMEM>>>(P);
    }

    for (int l = 0; l < NL; l++) {
        const float* h0f = y0 + l * HID;  // fp32 h (skip-blend input), lda = OW
        const float* h1f = y1 + l * HID;
        const __half* wc0 = wcat0 + (size_t)l * HID * LD0;
        const __half* wc1 = wcat1 + (size_t)l * HID * LD1;
        const float* bc0 = bcat0 + (size_t)l * LD0;
        const float* bc1 = bcat1 + (size_t)l * LD1;
        const __half* wal = wa + (size_t)l * 2 * HID * HID;

        // ---- fused qkv projections (fp16 A path; all outputs fp16)
        {
            GemmPair P;
            P.nb0 = NB0;
            P.s[0] = {nullptr, 0, h0h, wc0, bc0, nullptr, 0, q0, kv0, KV0, N0, LD0 / GBN, nullptr, 0, nullptr};
            P.s[1] = {nullptr, 0, h1h, wc1, bc1, nullptr, 0, q1, kv1, KV1, N1, LD1 / GBN, nullptr, 0, nullptr};
            gemm_tc<0,1,1,0><<<dim3(NB0 + NB1, LD1 / GBN), 512, GEMM_SMEM>>>(P);
        }

        cudaMemsetAsync(aggr, 0, (AGGR_FLOATS + SSUM_FLOATS) * sizeof(float), 0);

        // ---- single-pass fused edge stage
        Edge3 EP;
        float* aggr_tab[3] = {aggr,
                              aggr + (size_t)N1 * HID,
                              aggr + (size_t)(N1 + N0) * HID};
        EP.r[0] = {srcp[0], dstp[0], q1, kv0, kv0 + 128, KV0,
                   p_rel + (size_t)(l * 3 + 0) * NH, ssum, aggr_tab[0]};
        EP.r[1] = {srcp[1], dstp[1], q0, kv1, kv1 + 128, KV1,
                   p_rel + (size_t)(l * 3 + 1) * NH, ssum + (size_t)N0 * NH, aggr_tab[1]};
        EP.r[2] = {srcp[2], dstp[2], q1, kv1 + 256, kv1 + 384, KV1,
                   p_rel + (size_t)(l * 3 + 2) * NH, ssum + (size_t)2 * N0 * NH, aggr_tab[2]};
        EP.off1 = Ecnt[0];
        EP.off2 = Ecnt[0] + Ecnt[1];
        EP.total = Ecnt[0] + Ecnt[1] + Ecnt[2];
        int eBlocks = (EP.total + 7) / 8;
        edge_fused_k<<<eBlocks, 256>>>(EP);

        // ---- combine + gelu -> fp16
        int cThreads = (N0 + N1) * (HID / 4);
        combine_k<<<(cThreads + 255) / 256, 256>>>(aggr, ssum, aggh);

        // ---- output projection + skip blend (fp16 A; y fp32 + fp16 mirror)
        {
            GemmPair P;
            P.nb0 = NB0;
            P.s[0] = {nullptr, 0, aggh, wal, ba + (l * 2 + 0) * HID,
                      y0 + (l + 1) * HID, OW, h0h, nullptr, 0, N0, 1,
                      h0f, OW, skip + l * 2 + 0};
            P.s[1] = {nullptr, 0, aggh + (size_t)N0 * HID, wal + HID * HID,
                      ba + (l * 2 + 1) * HID,
                      y1 + (l + 1) * HID, OW, h1h, nullptr, 0, N1, 1,
                      h1f, OW, skip + l * 2 + 1};
            gemm_tc<2,1,0,1><<<dim3(NB0 + NB1, 1), 512, GEMM_SMEM>>>(P);
        }
    }
}